// round 1
// baseline (speedup 1.0000x reference)
#include <cuda_runtime.h>
#include <math_constants.h>

#define N_FILT 80
#define FDIM   251
#define L_IN   64000
#define P_OUT  63750   // 64000 - 251 + 1
#define N_BATCH 8

#define POS_TILE 1024
#define F_TILE   8
#define THREADS  256

__device__ float g_filters[N_FILT][FDIM];

// ---------------------------------------------------------------------------
// Block-wide reduction over 256 threads. mode: 0=max, 1=min, 2=sum
// All 256 threads must call (uniform control flow).
// ---------------------------------------------------------------------------
__device__ __forceinline__ float blk_reduce(float v, int mode) {
    __shared__ float red[THREADS];
    int t = threadIdx.x;
    __syncthreads();              // protect against WAR with previous use
    red[t] = v;
    __syncthreads();
    #pragma unroll
    for (int s = THREADS / 2; s > 0; s >>= 1) {
        if (t < s) {
            float a = red[t], b = red[t + s];
            red[t] = (mode == 0) ? fmaxf(a, b) : (mode == 1) ? fminf(a, b) : (a + b);
        }
        __syncthreads();
    }
    float r = red[0];
    __syncthreads();
    return r;
}

// _norm_pm1: y = 2*(v-mn)/(mx-mn+1e-6)-1 ; y -= mean(y)
__device__ __forceinline__ float norm_pm1(float v, bool act) {
    float mx = blk_reduce(act ? v : -CUDART_INF_F, 0);
    float mn = blk_reduce(act ? v :  CUDART_INF_F, 1);
    float y  = 2.0f * (v - mn) / (mx - mn + 1e-6f) - 1.0f;
    float s  = blk_reduce(act ? y : 0.0f, 2);
    return y - s * (1.0f / (float)FDIM);
}

// ---------------------------------------------------------------------------
// Kernel 1: build the 80 filters. One block per filter, 256 threads.
// ---------------------------------------------------------------------------
__global__ void build_filters_kernel(const float* __restrict__ nf1,
                                     const float* __restrict__ nf2,
                                     const float* __restrict__ nf3,
                                     const float* __restrict__ nf4,
                                     const float* __restrict__ amp1,
                                     const float* __restrict__ amp2) {
    __shared__ float ir1[FDIM];
    __shared__ float ir2[FDIM];

    const int f = blockIdx.x;
    const int i = threadIdx.x;
    const bool act = (i < FDIM);

    const float FS  = 16000.0f;
    const float MF  = 50.0f / 16000.0f;
    const float PIF = 3.14159265358979323846f;
    const float TWO_PI = 6.28318530717958647692f;

    float v1 = nf1[f], v2 = nf2[f], v3 = nf3[f], v4 = nf4[f];
    float f1 = fminf(fmaxf(fabsf(v1) + MF, 0.0f), 0.5f);
    float f2 = fminf(fmaxf(f1 + fabsf(v2 - f1) + MF, 0.0f), 0.5f);
    float f3 = fminf(fmaxf(fabsf(v3) + MF, 0.0f), 0.5f);
    float f4 = fminf(fmaxf(f3 + fabsf(v4 - f3) + MF, 0.0f), 0.5f);
    float a1 = fabsf(amp1[f]);
    float a2 = fabsf(amp2[f]);

    float ti = act ? (float)(i + 1) * (1.0f / FS) : 0.0f;
    float t2 = ti * ti;

    // ---- ir1 = norm_pm1(gauss(a1, f1*FS, f2*FS, t)) ----
    {
        float F1 = f1 * FS, F2 = f2 * FS;
        float fc = 0.5f * (F1 + F2);
        float bw = F2 - F1;
        float pb = PIF * bw;
        float ce = -2.0f * pb * pb;
        float v  = a1 * expf(ce * t2) * cosf((TWO_PI * fc) * ti);
        v = norm_pm1(v, act);
        if (act) ir1[i] = v;
    }
    // ---- ir2 = norm_pm1(gauss(a2, f3*FS, f4*FS, t)) ----
    {
        float F1 = f3 * FS, F2 = f4 * FS;
        float fc = 0.5f * (F1 + F2);
        float bw = F2 - F1;
        float pb = PIF * bw;
        float ce = -2.0f * pb * pb;
        float v  = a2 * expf(ce * t2) * cosf((TWO_PI * fc) * ti);
        v = norm_pm1(v, act);
        if (act) ir2[i] = v;
    }
    __syncthreads();

    // ---- cascade: casc[n] = sum_j ir1[n+j-125] * ir2[j]  (zero-padded) ----
    float c = 0.0f;
    if (act) {
        #pragma unroll 4
        for (int j = 0; j < FDIM; j++) {
            int idx = i + j - (FDIM / 2);
            if (idx >= 0 && idx < FDIM) c += ir1[idx] * ir2[j];
        }
    }
    c = norm_pm1(c, act);

    // ---- window (Hamming via linspace(0, 251, 251)) and store ----
    if (act) {
        float nv  = (float)i * ((float)FDIM / (float)(FDIM - 1)); // 251/250 step
        float win = 0.54f - 0.46f * cosf(TWO_PI * nv * (1.0f / (float)FDIM));
        g_filters[f][i] = c * win;
    }
}

// ---------------------------------------------------------------------------
// Kernel 2: main convolution.
// Block = (POS_TILE positions) x (F_TILE filters) for one batch element.
// Each thread: 4 positions (stride 256) x 8 filters = 32 fp32 accumulators.
// ---------------------------------------------------------------------------
__global__ __launch_bounds__(THREADS) void conv_kernel(const float* __restrict__ x,
                                                       float* __restrict__ out) {
    __shared__ float xs[POS_TILE + FDIM - 1];   // 1274 floats
    __shared__ float wf[F_TILE][FDIM + 1];      // 252 stride

    const int t  = threadIdx.x;
    const int p0 = blockIdx.x * POS_TILE;
    const int b  = blockIdx.y;
    const int f0 = blockIdx.z * F_TILE;

    const float* xb = x + (size_t)b * L_IN;

    // Load x tile (zero-fill past end of signal)
    for (int i = t; i < POS_TILE + FDIM - 1; i += THREADS) {
        int g = p0 + i;
        xs[i] = (g < L_IN) ? xb[g] : 0.0f;
    }
    // Load 8 filters
    for (int i = t; i < F_TILE * FDIM; i += THREADS) {
        int f = i / FDIM, k = i - f * FDIM;
        wf[f][k] = g_filters[f0 + f][k];
    }
    __syncthreads();

    float acc[F_TILE][4];
    #pragma unroll
    for (int f = 0; f < F_TILE; f++)
        #pragma unroll
        for (int v = 0; v < 4; v++) acc[f][v] = 0.0f;

    #pragma unroll 4
    for (int k = 0; k < FDIM; k++) {
        float xv0 = xs[t + 0 * THREADS + k];
        float xv1 = xs[t + 1 * THREADS + k];
        float xv2 = xs[t + 2 * THREADS + k];
        float xv3 = xs[t + 3 * THREADS + k];
        #pragma unroll
        for (int f = 0; f < F_TILE; f++) {
            float w = wf[f][k];
            acc[f][0] = fmaf(w, xv0, acc[f][0]);
            acc[f][1] = fmaf(w, xv1, acc[f][1]);
            acc[f][2] = fmaf(w, xv2, acc[f][2]);
            acc[f][3] = fmaf(w, xv3, acc[f][3]);
        }
    }

    // Store (guard tail tile)
    #pragma unroll
    for (int f = 0; f < F_TILE; f++) {
        float* ob = out + ((size_t)b * N_FILT + (f0 + f)) * P_OUT;
        #pragma unroll
        for (int v = 0; v < 4; v++) {
            int p = p0 + t + v * THREADS;
            if (p < P_OUT) ob[p] = acc[f][v];
        }
    }
}

// ---------------------------------------------------------------------------
// Launch
// ---------------------------------------------------------------------------
extern "C" void kernel_launch(void* const* d_in, const int* in_sizes, int n_in,
                              void* d_out, int out_size) {
    const float* x    = (const float*)d_in[0];
    const float* nf1  = (const float*)d_in[1];
    const float* nf2  = (const float*)d_in[2];
    const float* nf3  = (const float*)d_in[3];
    const float* nf4  = (const float*)d_in[4];
    const float* amp1 = (const float*)d_in[5];
    const float* amp2 = (const float*)d_in[6];
    float* out = (float*)d_out;

    build_filters_kernel<<<N_FILT, THREADS>>>(nf1, nf2, nf3, nf4, amp1, amp2);

    dim3 grid((P_OUT + POS_TILE - 1) / POS_TILE,  // 63
              N_BATCH,                            // 8
              N_FILT / F_TILE);                   // 10
    conv_kernel<<<grid, THREADS>>>(x, out);
}

// round 2
// speedup vs baseline: 1.2320x; 1.2320x over previous
#include <cuda_runtime.h>
#include <math_constants.h>

#define N_FILT 80
#define FDIM   251
#define L_IN   64000
#define P_OUT  63750   // 64000 - 251 + 1
#define N_BATCH 8

#define THREADS  256
#define F_TILE   8
#define VP       8              // packed position-pairs per thread
#define PAIR_OFF 2048           // second element of each pair is +2048 positions
#define POS_TILE 4096           // VP*THREADS*2 positions per block

__device__ float g_filters[N_FILT][FDIM];

// ---------------------------------------------------------------------------
// packed fp32x2 helpers (Blackwell FFMA2 — only reachable via PTX)
// ---------------------------------------------------------------------------
__device__ __forceinline__ void ffma2(unsigned long long& acc,
                                      unsigned long long a,
                                      unsigned long long b) {
    asm("fma.rn.f32x2 %0, %1, %2, %0;" : "+l"(acc) : "l"(a), "l"(b));
}
__device__ __forceinline__ unsigned long long pack2(float lo, float hi) {
    unsigned long long r;
    asm("mov.b64 %0, {%1, %2};" : "=l"(r) : "f"(lo), "f"(hi));
    return r;
}

// ---------------------------------------------------------------------------
// Block-wide reduction over 256 threads. mode: 0=max, 1=min, 2=sum
// ---------------------------------------------------------------------------
__device__ __forceinline__ float blk_reduce(float v, int mode) {
    __shared__ float red[THREADS];
    int t = threadIdx.x;
    __syncthreads();
    red[t] = v;
    __syncthreads();
    #pragma unroll
    for (int s = THREADS / 2; s > 0; s >>= 1) {
        if (t < s) {
            float a = red[t], b = red[t + s];
            red[t] = (mode == 0) ? fmaxf(a, b) : (mode == 1) ? fminf(a, b) : (a + b);
        }
        __syncthreads();
    }
    float r = red[0];
    __syncthreads();
    return r;
}

__device__ __forceinline__ float norm_pm1(float v, bool act) {
    float mx = blk_reduce(act ? v : -CUDART_INF_F, 0);
    float mn = blk_reduce(act ? v :  CUDART_INF_F, 1);
    float y  = 2.0f * (v - mn) / (mx - mn + 1e-6f) - 1.0f;
    float s  = blk_reduce(act ? y : 0.0f, 2);
    return y - s * (1.0f / (float)FDIM);
}

// ---------------------------------------------------------------------------
// Kernel 1: build the 80 filters. One block per filter, 256 threads.
// ---------------------------------------------------------------------------
__global__ void build_filters_kernel(const float* __restrict__ nf1,
                                     const float* __restrict__ nf2,
                                     const float* __restrict__ nf3,
                                     const float* __restrict__ nf4,
                                     const float* __restrict__ amp1,
                                     const float* __restrict__ amp2) {
    __shared__ float ir1[FDIM];
    __shared__ float ir2[FDIM];

    const int f = blockIdx.x;
    const int i = threadIdx.x;
    const bool act = (i < FDIM);

    const float FS  = 16000.0f;
    const float MF  = 50.0f / 16000.0f;
    const float PIF = 3.14159265358979323846f;
    const float TWO_PI = 6.28318530717958647692f;

    float v1 = nf1[f], v2 = nf2[f], v3 = nf3[f], v4 = nf4[f];
    float f1 = fminf(fmaxf(fabsf(v1) + MF, 0.0f), 0.5f);
    float f2 = fminf(fmaxf(f1 + fabsf(v2 - f1) + MF, 0.0f), 0.5f);
    float f3 = fminf(fmaxf(fabsf(v3) + MF, 0.0f), 0.5f);
    float f4 = fminf(fmaxf(f3 + fabsf(v4 - f3) + MF, 0.0f), 0.5f);
    float a1 = fabsf(amp1[f]);
    float a2 = fabsf(amp2[f]);

    float ti = act ? (float)(i + 1) * (1.0f / FS) : 0.0f;
    float t2 = ti * ti;

    {
        float F1 = f1 * FS, F2 = f2 * FS;
        float fc = 0.5f * (F1 + F2);
        float bw = F2 - F1;
        float pb = PIF * bw;
        float ce = -2.0f * pb * pb;
        float v  = a1 * expf(ce * t2) * cosf((TWO_PI * fc) * ti);
        v = norm_pm1(v, act);
        if (act) ir1[i] = v;
    }
    {
        float F1 = f3 * FS, F2 = f4 * FS;
        float fc = 0.5f * (F1 + F2);
        float bw = F2 - F1;
        float pb = PIF * bw;
        float ce = -2.0f * pb * pb;
        float v  = a2 * expf(ce * t2) * cosf((TWO_PI * fc) * ti);
        v = norm_pm1(v, act);
        if (act) ir2[i] = v;
    }
    __syncthreads();

    float c = 0.0f;
    if (act) {
        #pragma unroll 4
        for (int j = 0; j < FDIM; j++) {
            int idx = i + j - (FDIM / 2);
            if (idx >= 0 && idx < FDIM) c += ir1[idx] * ir2[j];
        }
    }
    c = norm_pm1(c, act);

    if (act) {
        float nv  = (float)i * ((float)FDIM / (float)(FDIM - 1));
        float win = 0.54f - 0.46f * cosf(TWO_PI * nv * (1.0f / (float)FDIM));
        g_filters[f][i] = c * win;
    }
}

// ---------------------------------------------------------------------------
// Kernel 2: main convolution, packed f32x2.
// Block covers POS_TILE=4096 positions x F_TILE=8 filters for one batch elem.
// Thread t, pair j: positions (p0 + t + j*256, p0 + t + j*256 + 2048).
// x tile pre-interleaved as float2 so one LDS.64 yields a packed operand.
// ---------------------------------------------------------------------------
__global__ __launch_bounds__(THREADS) void conv_kernel(const float* __restrict__ x,
                                                       float* __restrict__ out) {
    __shared__ float2 xs2[PAIR_OFF + FDIM - 1];   // 2298 float2 = 18384 B
    __shared__ float  wf[FDIM][F_TILE];           // 8032 B, broadcast reads

    const int t  = threadIdx.x;
    const int p0 = blockIdx.x * POS_TILE;
    const int b  = blockIdx.y;
    const int f0 = blockIdx.z * F_TILE;

    const float* xb = x + (size_t)b * L_IN;

    // Interleaved x tile: xs2[i] = { x[p0+i], x[p0+PAIR_OFF+i] }, zero-padded.
    for (int i = t; i < PAIR_OFF + FDIM - 1; i += THREADS) {
        int ga = p0 + i;
        int gb = ga + PAIR_OFF;
        float a = (ga < L_IN) ? xb[ga] : 0.0f;
        float c = (gb < L_IN) ? xb[gb] : 0.0f;
        xs2[i] = make_float2(a, c);
    }
    // Filters, [k][f] layout so the per-k reads are consecutive broadcasts.
    for (int i = t; i < F_TILE * FDIM; i += THREADS) {
        int f = i & (F_TILE - 1), k = i >> 3;
        wf[k][f] = g_filters[f0 + f][k];
    }
    __syncthreads();

    unsigned long long acc[F_TILE][VP];
    #pragma unroll
    for (int f = 0; f < F_TILE; f++)
        #pragma unroll
        for (int j = 0; j < VP; j++) acc[f][j] = 0ULL;

    const unsigned long long* xsu =
        reinterpret_cast<const unsigned long long*>(xs2);

    #pragma unroll 2
    for (int k = 0; k < FDIM; k++) {
        unsigned long long xv[VP];
        #pragma unroll
        for (int j = 0; j < VP; j++) xv[j] = xsu[t + j * THREADS + k];

        #pragma unroll
        for (int f = 0; f < F_TILE; f++) {
            float w = wf[k][f];
            unsigned long long w2 = pack2(w, w);
            #pragma unroll
            for (int j = 0; j < VP; j++) ffma2(acc[f][j], w2, xv[j]);
        }
    }

    // Store: lane .x -> position p, lane .y -> position p + PAIR_OFF.
    #pragma unroll
    for (int f = 0; f < F_TILE; f++) {
        float* ob = out + ((size_t)b * N_FILT + (f0 + f)) * P_OUT;
        #pragma unroll
        for (int j = 0; j < VP; j++) {
            float2 r = *reinterpret_cast<float2*>(&acc[f][j]);
            int p = p0 + t + j * THREADS;
            if (p < P_OUT) ob[p] = r.x;
            int p2 = p + PAIR_OFF;
            if (p2 < P_OUT) ob[p2] = r.y;
        }
    }
}

// ---------------------------------------------------------------------------
// Launch
// ---------------------------------------------------------------------------
extern "C" void kernel_launch(void* const* d_in, const int* in_sizes, int n_in,
                              void* d_out, int out_size) {
    const float* x    = (const float*)d_in[0];
    const float* nf1  = (const float*)d_in[1];
    const float* nf2  = (const float*)d_in[2];
    const float* nf3  = (const float*)d_in[3];
    const float* nf4  = (const float*)d_in[4];
    const float* amp1 = (const float*)d_in[5];
    const float* amp2 = (const float*)d_in[6];
    float* out = (float*)d_out;

    build_filters_kernel<<<N_FILT, THREADS>>>(nf1, nf2, nf3, nf4, amp1, amp2);

    dim3 grid((P_OUT + POS_TILE - 1) / POS_TILE,  // 16
              N_BATCH,                            // 8
              N_FILT / F_TILE);                   // 10
    conv_kernel<<<grid, THREADS>>>(x, out);
}

// round 4
// speedup vs baseline: 1.2453x; 1.0108x over previous
#include <cuda_runtime.h>
#include <cuda_fp16.h>
#include <math_constants.h>
#include <cstdint>

#define N_FILT 80
#define FDIM   251
#define L_IN   64000
#define P_OUT  63750
#define N_BATCH 8

#define MPAD   128
#define KPAD   256
#define NT     256          // positions per CTA
#define THREADS 256
#define NSTEPS  16          // KPAD / 16

// dynamic smem layout (bytes)
#define WS_H_OFF 0
#define WS_L_OFF 40960      // A-lo delta = 40960
#define XC_H_OFF 81920
#define XO_H_OFF 83008      // xc->xo delta = 1088
#define XC_L_OFF 84096      // B-lo delta  = 2176
#define XO_L_OFF 85184
#define SMEM_TOTAL 86272
#define XBUF 528

__device__ float  g_filters[N_FILT][FDIM];
__device__ __half g_wh[MPAD][KPAD];
__device__ __half g_wl[MPAD][KPAD];

// ============================ PTX helpers ============================
__device__ __forceinline__ uint32_t smem_u32(const void* p) {
    uint32_t a;
    asm("{ .reg .u64 t; cvta.to.shared.u64 t, %1; cvt.u32.u64 %0, t; }"
        : "=r"(a) : "l"(p));
    return a;
}
__device__ __forceinline__ uint32_t lds32(uint32_t a) {
    uint32_t v;
    asm volatile("ld.shared.b32 %0, [%1];" : "=r"(v) : "r"(a));
    return v;
}
__device__ __forceinline__ void ldsm4(uint32_t* r, uint32_t a) {
    asm volatile("ldmatrix.sync.aligned.m8n8.x4.shared.b16 {%0,%1,%2,%3}, [%4];"
                 : "=r"(r[0]), "=r"(r[1]), "=r"(r[2]), "=r"(r[3]) : "r"(a));
}
__device__ __forceinline__ void mma16816(float* d, const uint32_t* a,
                                         uint32_t b0, uint32_t b1) {
    asm volatile(
        "mma.sync.aligned.m16n8k16.row.col.f32.f16.f16.f32 "
        "{%0,%1,%2,%3}, {%4,%5,%6,%7}, {%8,%9}, {%0,%1,%2,%3};"
        : "+f"(d[0]), "+f"(d[1]), "+f"(d[2]), "+f"(d[3])
        : "r"(a[0]), "r"(a[1]), "r"(a[2]), "r"(a[3]), "r"(b0), "r"(b1));
}

// ========================= filter construction =========================
__device__ __forceinline__ float blk_reduce(float v, int mode) {
    __shared__ float red[THREADS];
    int t = threadIdx.x;
    __syncthreads();
    red[t] = v;
    __syncthreads();
    #pragma unroll
    for (int s = THREADS / 2; s > 0; s >>= 1) {
        if (t < s) {
            float a = red[t], b = red[t + s];
            red[t] = (mode == 0) ? fmaxf(a, b) : (mode == 1) ? fminf(a, b) : (a + b);
        }
        __syncthreads();
    }
    float r = red[0];
    __syncthreads();
    return r;
}
__device__ __forceinline__ float norm_pm1(float v, bool act) {
    float mx = blk_reduce(act ? v : -CUDART_INF_F, 0);
    float mn = blk_reduce(act ? v :  CUDART_INF_F, 1);
    float y  = 2.0f * (v - mn) / (mx - mn + 1e-6f) - 1.0f;
    float s  = blk_reduce(act ? y : 0.0f, 2);
    return y - s * (1.0f / (float)FDIM);
}

__global__ void build_filters_kernel(const float* __restrict__ nf1,
                                     const float* __restrict__ nf2,
                                     const float* __restrict__ nf3,
                                     const float* __restrict__ nf4,
                                     const float* __restrict__ amp1,
                                     const float* __restrict__ amp2) {
    __shared__ float ir1[FDIM];
    __shared__ float ir2[FDIM];
    const int f = blockIdx.x;
    const int i = threadIdx.x;
    const bool act = (i < FDIM);
    const float FS = 16000.0f, MF = 50.0f / 16000.0f;
    const float PIF = 3.14159265358979323846f, TWO_PI = 6.28318530717958647692f;

    float f1 = fminf(fmaxf(fabsf(nf1[f]) + MF, 0.0f), 0.5f);
    float f2 = fminf(fmaxf(f1 + fabsf(nf2[f] - f1) + MF, 0.0f), 0.5f);
    float f3 = fminf(fmaxf(fabsf(nf3[f]) + MF, 0.0f), 0.5f);
    float f4 = fminf(fmaxf(f3 + fabsf(nf4[f] - f3) + MF, 0.0f), 0.5f);
    float a1 = fabsf(amp1[f]), a2 = fabsf(amp2[f]);
    float ti = act ? (float)(i + 1) * (1.0f / FS) : 0.0f;
    float t2 = ti * ti;
    {
        float F1 = f1 * FS, F2 = f2 * FS, fc = 0.5f * (F1 + F2), bw = F2 - F1;
        float pb = PIF * bw, ce = -2.0f * pb * pb;
        float v = a1 * expf(ce * t2) * cosf((TWO_PI * fc) * ti);
        v = norm_pm1(v, act);
        if (act) ir1[i] = v;
    }
    {
        float F1 = f3 * FS, F2 = f4 * FS, fc = 0.5f * (F1 + F2), bw = F2 - F1;
        float pb = PIF * bw, ce = -2.0f * pb * pb;
        float v = a2 * expf(ce * t2) * cosf((TWO_PI * fc) * ti);
        v = norm_pm1(v, act);
        if (act) ir2[i] = v;
    }
    __syncthreads();
    float c = 0.0f;
    if (act) {
        #pragma unroll 4
        for (int j = 0; j < FDIM; j++) {
            int idx = i + j - (FDIM / 2);
            if (idx >= 0 && idx < FDIM) c += ir1[idx] * ir2[j];
        }
    }
    c = norm_pm1(c, act);
    if (act) {
        float nv  = (float)i * ((float)FDIM / (float)(FDIM - 1));
        float win = 0.54f - 0.46f * cosf(TWO_PI * nv * (1.0f / (float)FDIM));
        g_filters[f][i] = c * win;
    }
}

// ========================= prep: fp16 hi/lo weight split =========================
__global__ void prep_w_kernel() {
    int m = blockIdx.x;        // 0..127
    int k = threadIdx.x;       // 0..255
    float v = (m < N_FILT && k < FDIM) ? g_filters[m][k] : 0.0f;
    __half h = __float2half_rn(v);
    __half l = __float2half_rn(v - __half2float(h));
    g_wh[m][k] = h;
    g_wl[m][k] = l;
}

// ========================= main HMMA conv =========================
extern __shared__ __align__(16) char smraw[];

__global__ __launch_bounds__(THREADS) void conv_mma_kernel(const float* __restrict__ x,
                                                           float* __restrict__ out) {
    const int t   = threadIdx.x;
    const int wid = t >> 5;
    const int lid = t & 31;
    const int gid = lid >> 2;      // 0..7
    const int tg  = lid & 3;       // 0..3
    const int n0  = blockIdx.x * NT;
    const int b   = blockIdx.y;
    const int nw  = wid * 32;      // warp's position offset within tile

    const uint32_t sbase = smem_u32(smraw);

    // ---- load weights hi+lo into smem (80 rows x 256 halves each) ----
    {
        const uint4* gh = reinterpret_cast<const uint4*>(&g_wh[0][0]);
        const uint4* gl = reinterpret_cast<const uint4*>(&g_wl[0][0]);
        uint4* sh = reinterpret_cast<uint4*>(smraw + WS_H_OFF);
        uint4* sl = reinterpret_cast<uint4*>(smraw + WS_L_OFF);
        #pragma unroll
        for (int i = 0; i < 10; i++) {           // 2560 uint4 / 256 thr
            sh[t + i * THREADS] = gh[t + i * THREADS];
            sl[t + i * THREADS] = gl[t + i * THREADS];
        }
    }
    // ---- load x window, split hi/lo, plus 1-half-shifted copies ----
    {
        const float* xb = x + (size_t)b * L_IN;
        __half* xch = reinterpret_cast<__half*>(smraw + XC_H_OFF);
        __half* xoh = reinterpret_cast<__half*>(smraw + XO_H_OFF);
        __half* xcl = reinterpret_cast<__half*>(smraw + XC_L_OFF);
        __half* xol = reinterpret_cast<__half*>(smraw + XO_L_OFF);
        #pragma unroll
        for (int i = t; i < XBUF; i += THREADS) {
            int g  = n0 + i;
            float v  = (g < L_IN) ? xb[g] : 0.0f;
            int g2 = g + 1;
            float v2 = (g2 < L_IN) ? xb[g2] : 0.0f;
            __half h  = __float2half_rn(v);
            __half l  = __float2half_rn(v - __half2float(h));
            __half h2 = __float2half_rn(v2);
            __half l2 = __float2half_rn(v2 - __half2float(h2));
            xch[i] = h;  xcl[i] = l;
            xoh[i] = h2; xol[i] = l2;
        }
    }
    __syncthreads();

    // ---- per-lane address bases ----
    // A (ldmatrix): lane l -> row (l&7) + ((l>>3)&1)*8, k-byte ((l>>3)>>1)*16
    const int sub = lid >> 3;
    const uint32_t a_base = sbase + WS_H_OFF
        + (uint32_t)(((lid & 7) + (sub & 1) * 8) * 512 + (sub >> 1) * 16);
    // B: half index o = k0 + 2*tg + nw + 8*j + gid ; sel = parity (const per lane)
    const int sel = gid & 1;
    const uint32_t b_base = sbase + (sel ? XO_H_OFF : XC_H_OFF)
        + (uint32_t)(2 * (2 * tg + nw + gid - sel));

    float acc[5][4][4];
    #pragma unroll
    for (int i = 0; i < 5; i++)
        #pragma unroll
        for (int j = 0; j < 4; j++)
            #pragma unroll
            for (int c = 0; c < 4; c++) acc[i][j][c] = 0.0f;

    #pragma unroll 2
    for (int s = 0; s < NSTEPS; s++) {
        const uint32_t kb = (uint32_t)s * 32;   // k0 * 2 bytes

        uint32_t bh0[4], bh1[4], bl0[4], bl1[4];
        #pragma unroll
        for (int j = 0; j < 4; j++) {
            uint32_t a = b_base + kb + (uint32_t)(j * 16);
            bh0[j] = lds32(a);
            bh1[j] = lds32(a + 16);
            bl0[j] = lds32(a + 2176);
            bl1[j] = lds32(a + 2192);
        }

        #pragma unroll
        for (int i = 0; i < 5; i++) {
            uint32_t ah[4], al[4];
            uint32_t aa = a_base + (uint32_t)(i * 8192) + kb;
            ldsm4(ah, aa);
            ldsm4(al, aa + 40960);
            #pragma unroll
            for (int j = 0; j < 4; j++) {
                mma16816(acc[i][j], ah, bh0[j], bh1[j]);
                mma16816(acc[i][j], ah, bl0[j], bl1[j]);
                mma16816(acc[i][j], al, bh0[j], bh1[j]);
            }
        }
    }

    // ---- epilogue: direct stores from fragments ----
    #pragma unroll
    for (int i = 0; i < 5; i++) {
        const int f0 = 16 * i + gid;
        float* o0 = out + ((size_t)b * N_FILT + f0) * P_OUT;
        float* o1 = out + ((size_t)b * N_FILT + f0 + 8) * P_OUT;
        #pragma unroll
        for (int j = 0; j < 4; j++) {
            int p = n0 + nw + 8 * j + 2 * tg;
            if (p < P_OUT) {
                *reinterpret_cast<float2*>(o0 + p) =
                    make_float2(acc[i][j][0], acc[i][j][1]);
                *reinterpret_cast<float2*>(o1 + p) =
                    make_float2(acc[i][j][2], acc[i][j][3]);
            }
        }
    }
}

// ================================ launch ================================
extern "C" void kernel_launch(void* const* d_in, const int* in_sizes, int n_in,
                              void* d_out, int out_size) {
    const float* x    = (const float*)d_in[0];
    const float* nf1  = (const float*)d_in[1];
    const float* nf2  = (const float*)d_in[2];
    const float* nf3  = (const float*)d_in[3];
    const float* nf4  = (const float*)d_in[4];
    const float* amp1 = (const float*)d_in[5];
    const float* amp2 = (const float*)d_in[6];
    float* out = (float*)d_out;

    static bool attr_set = false;
    if (!attr_set) {
        cudaFuncSetAttribute(conv_mma_kernel,
                             cudaFuncAttributeMaxDynamicSharedMemorySize, SMEM_TOTAL);
        attr_set = true;
    }

    build_filters_kernel<<<N_FILT, THREADS>>>(nf1, nf2, nf3, nf4, amp1, amp2);
    prep_w_kernel<<<MPAD, KPAD>>>();

    dim3 grid((P_OUT + NT - 1) / NT, N_BATCH);   // 250 x 8
    conv_mma_kernel<<<grid, THREADS, SMEM_TOTAL>>>(x, out);
}

// round 5
// speedup vs baseline: 2.4982x; 2.0061x over previous
#include <cuda_runtime.h>
#include <cuda_fp16.h>
#include <math_constants.h>
#include <cstdint>

#define N_FILT 80
#define FDIM   251
#define L_IN   64000
#define P_OUT  63750
#define N_BATCH 8

#define MPAD   128
#define KPAD   256
#define NT     256          // positions per CTA
#define THREADS 256
#define NSTEPS  16          // KPAD / 16

// A row stride padded to 528B (264 halves): 132 words = 4 banks shift/row
#define A_STRIDE_B 528
// dynamic smem layout (bytes)
#define WS_H_OFF 0
#define WS_L_OFF 42240      // 80 * 528
#define XC_H_OFF 84480
#define XO_H_OFF 85568      // +1088
#define XC_L_OFF 86656      // B hi->lo delta = 2176
#define XO_L_OFF 87744
#define SMEM_TOTAL 88832
#define XBUF 528

__device__ float  g_filters[N_FILT][FDIM];
__device__ __half g_wh[MPAD][KPAD];
__device__ __half g_wl[MPAD][KPAD];

// ============================ PTX helpers ============================
__device__ __forceinline__ uint32_t smem_u32(const void* p) {
    uint32_t a;
    asm("{ .reg .u64 t; cvta.to.shared.u64 t, %1; cvt.u32.u64 %0, t; }"
        : "=r"(a) : "l"(p));
    return a;
}
__device__ __forceinline__ uint32_t lds32(uint32_t a) {
    uint32_t v;
    asm volatile("ld.shared.b32 %0, [%1];" : "=r"(v) : "r"(a));
    return v;
}
__device__ __forceinline__ void ldsm4(uint32_t* r, uint32_t a) {
    asm volatile("ldmatrix.sync.aligned.m8n8.x4.shared.b16 {%0,%1,%2,%3}, [%4];"
                 : "=r"(r[0]), "=r"(r[1]), "=r"(r[2]), "=r"(r[3]) : "r"(a));
}
__device__ __forceinline__ void mma16816(float* d, const uint32_t* a,
                                         uint32_t b0, uint32_t b1) {
    asm volatile(
        "mma.sync.aligned.m16n8k16.row.col.f32.f16.f16.f32 "
        "{%0,%1,%2,%3}, {%4,%5,%6,%7}, {%8,%9}, {%0,%1,%2,%3};"
        : "+f"(d[0]), "+f"(d[1]), "+f"(d[2]), "+f"(d[3])
        : "r"(a[0]), "r"(a[1]), "r"(a[2]), "r"(a[3]), "r"(b0), "r"(b1));
}

// ========================= filter construction =========================
__device__ __forceinline__ float blk_reduce(float v, int mode) {
    __shared__ float red[THREADS];
    int t = threadIdx.x;
    __syncthreads();
    red[t] = v;
    __syncthreads();
    #pragma unroll
    for (int s = THREADS / 2; s > 0; s >>= 1) {
        if (t < s) {
            float a = red[t], b = red[t + s];
            red[t] = (mode == 0) ? fmaxf(a, b) : (mode == 1) ? fminf(a, b) : (a + b);
        }
        __syncthreads();
    }
    float r = red[0];
    __syncthreads();
    return r;
}
__device__ __forceinline__ float norm_pm1(float v, bool act) {
    float mx = blk_reduce(act ? v : -CUDART_INF_F, 0);
    float mn = blk_reduce(act ? v :  CUDART_INF_F, 1);
    float y  = 2.0f * (v - mn) / (mx - mn + 1e-6f) - 1.0f;
    float s  = blk_reduce(act ? y : 0.0f, 2);
    return y - s * (1.0f / (float)FDIM);
}

__global__ void build_filters_kernel(const float* __restrict__ nf1,
                                     const float* __restrict__ nf2,
                                     const float* __restrict__ nf3,
                                     const float* __restrict__ nf4,
                                     const float* __restrict__ amp1,
                                     const float* __restrict__ amp2) {
    __shared__ float ir1[FDIM];
    __shared__ float ir2[FDIM];
    const int f = blockIdx.x;
    const int i = threadIdx.x;
    const bool act = (i < FDIM);
    const float FS = 16000.0f, MF = 50.0f / 16000.0f;
    const float PIF = 3.14159265358979323846f, TWO_PI = 6.28318530717958647692f;

    float f1 = fminf(fmaxf(fabsf(nf1[f]) + MF, 0.0f), 0.5f);
    float f2 = fminf(fmaxf(f1 + fabsf(nf2[f] - f1) + MF, 0.0f), 0.5f);
    float f3 = fminf(fmaxf(fabsf(nf3[f]) + MF, 0.0f), 0.5f);
    float f4 = fminf(fmaxf(f3 + fabsf(nf4[f] - f3) + MF, 0.0f), 0.5f);
    float a1 = fabsf(amp1[f]), a2 = fabsf(amp2[f]);
    float ti = act ? (float)(i + 1) * (1.0f / FS) : 0.0f;
    float t2 = ti * ti;
    {
        float F1 = f1 * FS, F2 = f2 * FS, fc = 0.5f * (F1 + F2), bw = F2 - F1;
        float pb = PIF * bw, ce = -2.0f * pb * pb;
        float v = a1 * expf(ce * t2) * cosf((TWO_PI * fc) * ti);
        v = norm_pm1(v, act);
        if (act) ir1[i] = v;
    }
    {
        float F1 = f3 * FS, F2 = f4 * FS, fc = 0.5f * (F1 + F2), bw = F2 - F1;
        float pb = PIF * bw, ce = -2.0f * pb * pb;
        float v = a2 * expf(ce * t2) * cosf((TWO_PI * fc) * ti);
        v = norm_pm1(v, act);
        if (act) ir2[i] = v;
    }
    __syncthreads();
    float c = 0.0f;
    if (act) {
        #pragma unroll 4
        for (int j = 0; j < FDIM; j++) {
            int idx = i + j - (FDIM / 2);
            if (idx >= 0 && idx < FDIM) c += ir1[idx] * ir2[j];
        }
    }
    c = norm_pm1(c, act);
    if (act) {
        float nv  = (float)i * ((float)FDIM / (float)(FDIM - 1));
        float win = 0.54f - 0.46f * cosf(TWO_PI * nv * (1.0f / (float)FDIM));
        g_filters[f][i] = c * win;
    }
}

// ========================= prep: fp16 hi/lo weight split =========================
__global__ void prep_w_kernel() {
    int m = blockIdx.x;        // 0..127
    int k = threadIdx.x;       // 0..255
    float v = (m < N_FILT && k < FDIM) ? g_filters[m][k] : 0.0f;
    __half h = __float2half_rn(v);
    __half l = __float2half_rn(v - __half2float(h));
    g_wh[m][k] = h;
    g_wl[m][k] = l;
}

// ========================= main HMMA conv =========================
extern __shared__ __align__(16) char smraw[];

__global__ __launch_bounds__(THREADS) void conv_mma_kernel(const float* __restrict__ x,
                                                           float* __restrict__ out) {
    const int t   = threadIdx.x;
    const int wid = t >> 5;
    const int lid = t & 31;
    const int gid = lid >> 2;      // 0..7
    const int tg  = lid & 3;       // 0..3
    const int n0  = blockIdx.x * NT;
    const int b   = blockIdx.y;
    const int nw  = wid * 32;      // warp's position offset within tile

    const uint32_t sbase = smem_u32(smraw);

    // ---- load weights hi+lo into smem, 528B padded row stride ----
    {
        const uint2* gh = reinterpret_cast<const uint2*>(&g_wh[0][0]);
        const uint2* gl = reinterpret_cast<const uint2*>(&g_wl[0][0]);
        // 80 rows x 64 uint2 (256 halves) each copy
        #pragma unroll
        for (int i = 0; i < 20; i++) {
            int idx = t + i * THREADS;          // 0..5119
            int m = idx >> 6, c = idx & 63;
            uint2 vh = gh[m * 64 + c];
            uint2 vl = gl[m * 64 + c];
            *reinterpret_cast<uint2*>(smraw + WS_H_OFF + m * A_STRIDE_B + c * 8) = vh;
            *reinterpret_cast<uint2*>(smraw + WS_L_OFF + m * A_STRIDE_B + c * 8) = vl;
        }
    }
    // ---- load x window, split hi/lo, plus 1-half-shifted copies ----
    {
        const float* xb = x + (size_t)b * L_IN;
        __half* xch = reinterpret_cast<__half*>(smraw + XC_H_OFF);
        __half* xoh = reinterpret_cast<__half*>(smraw + XO_H_OFF);
        __half* xcl = reinterpret_cast<__half*>(smraw + XC_L_OFF);
        __half* xol = reinterpret_cast<__half*>(smraw + XO_L_OFF);
        #pragma unroll
        for (int i = t; i < XBUF; i += THREADS) {
            int g  = n0 + i;
            float v  = (g < L_IN) ? xb[g] : 0.0f;
            int g2 = g + 1;
            float v2 = (g2 < L_IN) ? xb[g2] : 0.0f;
            __half h  = __float2half_rn(v);
            __half l  = __float2half_rn(v - __half2float(h));
            __half h2 = __float2half_rn(v2);
            __half l2 = __float2half_rn(v2 - __half2float(h2));
            xch[i] = h;  xcl[i] = l;
            xoh[i] = h2; xol[i] = l2;
        }
    }
    __syncthreads();

    // ---- per-lane address bases ----
    // A (ldmatrix): lane l -> row (l&7) + ((l>>3)&1)*8, k-byte ((l>>3)>>1)*16
    const int sub = lid >> 3;
    const uint32_t a_base = sbase + WS_H_OFF
        + (uint32_t)(((lid & 7) + (sub & 1) * 8) * A_STRIDE_B + (sub >> 1) * 16);
    // B: half index o = k0 + 2*tg + nw + 8*j + gid ; sel = parity (const per lane)
    const int sel = gid & 1;
    const uint32_t b_base = sbase + (sel ? XO_H_OFF : XC_H_OFF)
        + (uint32_t)(2 * (2 * tg + nw + gid - sel));

    float acc[5][4][4];
    #pragma unroll
    for (int i = 0; i < 5; i++)
        #pragma unroll
        for (int j = 0; j < 4; j++)
            #pragma unroll
            for (int c = 0; c < 4; c++) acc[i][j][c] = 0.0f;

    #pragma unroll 2
    for (int s = 0; s < NSTEPS; s++) {
        const uint32_t kb = (uint32_t)s * 32;   // k0 * 2 bytes

        // B fragments: b1[j] == b0[j+1], so only 5 hi + 5 lo distinct words
        uint32_t bh[5], bl[5];
        #pragma unroll
        for (int j = 0; j < 5; j++) {
            uint32_t a = b_base + kb + (uint32_t)(j * 16);
            bh[j] = lds32(a);
            bl[j] = lds32(a + 2176);
        }

        #pragma unroll
        for (int i = 0; i < 5; i++) {
            uint32_t ah[4], al[4];
            uint32_t aa = a_base + (uint32_t)(i * 16 * A_STRIDE_B) + kb;
            ldsm4(ah, aa);
            ldsm4(al, aa + (uint32_t)WS_L_OFF);
            #pragma unroll
            for (int j = 0; j < 4; j++) {
                mma16816(acc[i][j], ah, bh[j], bh[j + 1]);
                mma16816(acc[i][j], ah, bl[j], bl[j + 1]);
                mma16816(acc[i][j], al, bh[j], bh[j + 1]);
            }
        }
    }

    // ---- epilogue: direct stores from fragments ----
    #pragma unroll
    for (int i = 0; i < 5; i++) {
        const int f0 = 16 * i + gid;
        float* o0 = out + ((size_t)b * N_FILT + f0) * P_OUT;
        float* o1 = out + ((size_t)b * N_FILT + f0 + 8) * P_OUT;
        #pragma unroll
        for (int j = 0; j < 4; j++) {
            int p = n0 + nw + 8 * j + 2 * tg;
            if (p < P_OUT) {
                *reinterpret_cast<float2*>(o0 + p) =
                    make_float2(acc[i][j][0], acc[i][j][1]);
                *reinterpret_cast<float2*>(o1 + p) =
                    make_float2(acc[i][j][2], acc[i][j][3]);
            }
        }
    }
}

// ================================ launch ================================
extern "C" void kernel_launch(void* const* d_in, const int* in_sizes, int n_in,
                              void* d_out, int out_size) {
    const float* x    = (const float*)d_in[0];
    const float* nf1  = (const float*)d_in[1];
    const float* nf2  = (const float*)d_in[2];
    const float* nf3  = (const float*)d_in[3];
    const float* nf4  = (const float*)d_in[4];
    const float* amp1 = (const float*)d_in[5];
    const float* amp2 = (const float*)d_in[6];
    float* out = (float*)d_out;

    static bool attr_set = false;
    if (!attr_set) {
        cudaFuncSetAttribute(conv_mma_kernel,
                             cudaFuncAttributeMaxDynamicSharedMemorySize, SMEM_TOTAL);
        attr_set = true;
    }

    build_filters_kernel<<<N_FILT, THREADS>>>(nf1, nf2, nf3, nf4, amp1, amp2);
    prep_w_kernel<<<MPAD, KPAD>>>();

    dim3 grid((P_OUT + NT - 1) / NT, N_BATCH);   // 250 x 8
    conv_mma_kernel<<<grid, THREADS, SMEM_TOTAL>>>(x, out);
}

// round 6
// speedup vs baseline: 3.1537x; 1.2624x over previous
#include <cuda_runtime.h>
#include <cuda_fp16.h>
#include <math_constants.h>
#include <cstdint>

#define N_FILT 80
#define FDIM   251
#define L_IN   64000
#define P_OUT  63750
#define N_BATCH 8

#define MPAD   128
#define KPAD   256
#define NT     256          // positions per CTA
#define THREADS 256
#define NSTEPS  16          // KPAD / 16

// A row stride padded to 528B (264 halves): 132 words = 4 banks shift/row
#define A_STRIDE_B 528
// dynamic smem layout (bytes)
#define WS_OFF   0
#define XC_H_OFF 42240      // 80 * 528
#define XO_H_OFF 43328      // +1088
#define XC_L_OFF 44416      // B hi->lo delta = 2176
#define XO_L_OFF 45504
#define SMEM_TOTAL 46592
#define XBUF 528

__device__ float  g_filters[N_FILT][FDIM];
__device__ __half g_wh[MPAD][KPAD];

// ============================ PTX helpers ============================
__device__ __forceinline__ uint32_t smem_u32(const void* p) {
    uint32_t a;
    asm("{ .reg .u64 t; cvta.to.shared.u64 t, %1; cvt.u32.u64 %0, t; }"
        : "=r"(a) : "l"(p));
    return a;
}
__device__ __forceinline__ uint32_t lds32(uint32_t a) {
    uint32_t v;
    asm volatile("ld.shared.b32 %0, [%1];" : "=r"(v) : "r"(a));
    return v;
}
__device__ __forceinline__ void ldsm4(uint32_t* r, uint32_t a) {
    asm volatile("ldmatrix.sync.aligned.m8n8.x4.shared.b16 {%0,%1,%2,%3}, [%4];"
                 : "=r"(r[0]), "=r"(r[1]), "=r"(r[2]), "=r"(r[3]) : "r"(a));
}
__device__ __forceinline__ void mma16816(float* d, const uint32_t* a,
                                         uint32_t b0, uint32_t b1) {
    asm volatile(
        "mma.sync.aligned.m16n8k16.row.col.f32.f16.f16.f32 "
        "{%0,%1,%2,%3}, {%4,%5,%6,%7}, {%8,%9}, {%0,%1,%2,%3};"
        : "+f"(d[0]), "+f"(d[1]), "+f"(d[2]), "+f"(d[3])
        : "r"(a[0]), "r"(a[1]), "r"(a[2]), "r"(a[3]), "r"(b0), "r"(b1));
}

// ========================= filter construction =========================
__device__ __forceinline__ float blk_reduce(float v, int mode) {
    __shared__ float red[THREADS];
    int t = threadIdx.x;
    __syncthreads();
    red[t] = v;
    __syncthreads();
    #pragma unroll
    for (int s = THREADS / 2; s > 0; s >>= 1) {
        if (t < s) {
            float a = red[t], b = red[t + s];
            red[t] = (mode == 0) ? fmaxf(a, b) : (mode == 1) ? fminf(a, b) : (a + b);
        }
        __syncthreads();
    }
    float r = red[0];
    __syncthreads();
    return r;
}
__device__ __forceinline__ float norm_pm1(float v, bool act) {
    float mx = blk_reduce(act ? v : -CUDART_INF_F, 0);
    float mn = blk_reduce(act ? v :  CUDART_INF_F, 1);
    float y  = 2.0f * (v - mn) / (mx - mn + 1e-6f) - 1.0f;
    float s  = blk_reduce(act ? y : 0.0f, 2);
    return y - s * (1.0f / (float)FDIM);
}

__global__ void build_filters_kernel(const float* __restrict__ nf1,
                                     const float* __restrict__ nf2,
                                     const float* __restrict__ nf3,
                                     const float* __restrict__ nf4,
                                     const float* __restrict__ amp1,
                                     const float* __restrict__ amp2) {
    __shared__ float ir1[FDIM];
    __shared__ float ir2[FDIM];
    const int f = blockIdx.x;
    const int i = threadIdx.x;
    const bool act = (i < FDIM);
    const float FS = 16000.0f, MF = 50.0f / 16000.0f;
    const float PIF = 3.14159265358979323846f, TWO_PI = 6.28318530717958647692f;

    float f1 = fminf(fmaxf(fabsf(nf1[f]) + MF, 0.0f), 0.5f);
    float f2 = fminf(fmaxf(f1 + fabsf(nf2[f] - f1) + MF, 0.0f), 0.5f);
    float f3 = fminf(fmaxf(fabsf(nf3[f]) + MF, 0.0f), 0.5f);
    float f4 = fminf(fmaxf(f3 + fabsf(nf4[f] - f3) + MF, 0.0f), 0.5f);
    float a1 = fabsf(amp1[f]), a2 = fabsf(amp2[f]);
    float ti = act ? (float)(i + 1) * (1.0f / FS) : 0.0f;
    float t2 = ti * ti;
    {
        float F1 = f1 * FS, F2 = f2 * FS, fc = 0.5f * (F1 + F2), bw = F2 - F1;
        float pb = PIF * bw, ce = -2.0f * pb * pb;
        float v = a1 * expf(ce * t2) * cosf((TWO_PI * fc) * ti);
        v = norm_pm1(v, act);
        if (act) ir1[i] = v;
    }
    {
        float F1 = f3 * FS, F2 = f4 * FS, fc = 0.5f * (F1 + F2), bw = F2 - F1;
        float pb = PIF * bw, ce = -2.0f * pb * pb;
        float v = a2 * expf(ce * t2) * cosf((TWO_PI * fc) * ti);
        v = norm_pm1(v, act);
        if (act) ir2[i] = v;
    }
    __syncthreads();
    float c = 0.0f;
    if (act) {
        #pragma unroll 4
        for (int j = 0; j < FDIM; j++) {
            int idx = i + j - (FDIM / 2);
            if (idx >= 0 && idx < FDIM) c += ir1[idx] * ir2[j];
        }
    }
    c = norm_pm1(c, act);
    if (act) {
        float nv  = (float)i * ((float)FDIM / (float)(FDIM - 1));
        float win = 0.54f - 0.46f * cosf(TWO_PI * nv * (1.0f / (float)FDIM));
        g_filters[f][i] = c * win;
    }
}

// ========================= prep: fp16 weights =========================
__global__ void prep_w_kernel() {
    int m = blockIdx.x;        // 0..127
    int k = threadIdx.x;       // 0..255
    float v = (m < N_FILT && k < FDIM) ? g_filters[m][k] : 0.0f;
    g_wh[m][k] = __float2half_rn(v);
}

// ========================= main HMMA conv =========================
extern __shared__ __align__(16) char smraw[];

__global__ __launch_bounds__(THREADS) void conv_mma_kernel(const float* __restrict__ x,
                                                           float* __restrict__ out) {
    const int t   = threadIdx.x;
    const int wid = t >> 5;
    const int lid = t & 31;
    const int gid = lid >> 2;      // 0..7
    const int tg  = lid & 3;       // 0..3
    const int n0  = blockIdx.x * NT;
    const int b   = blockIdx.y;
    const int nw  = wid * 32;      // warp's position offset within tile

    const uint32_t sbase = smem_u32(smraw);

    // ---- load fp16 weights into smem, 528B padded row stride ----
    {
        const uint2* gh = reinterpret_cast<const uint2*>(&g_wh[0][0]);
        #pragma unroll
        for (int i = 0; i < 20; i++) {
            int idx = t + i * THREADS;          // 0..5119
            int m = idx >> 6, c = idx & 63;
            uint2 vh = gh[m * 64 + c];
            *reinterpret_cast<uint2*>(smraw + WS_OFF + m * A_STRIDE_B + c * 8) = vh;
        }
    }
    // ---- load x window, split hi/lo, plus 1-half-shifted copies ----
    {
        const float* xb = x + (size_t)b * L_IN;
        __half* xch = reinterpret_cast<__half*>(smraw + XC_H_OFF);
        __half* xoh = reinterpret_cast<__half*>(smraw + XO_H_OFF);
        __half* xcl = reinterpret_cast<__half*>(smraw + XC_L_OFF);
        __half* xol = reinterpret_cast<__half*>(smraw + XO_L_OFF);
        #pragma unroll
        for (int i = t; i < XBUF; i += THREADS) {
            int g  = n0 + i;
            float v  = (g < L_IN) ? xb[g] : 0.0f;
            int g2 = g + 1;
            float v2 = (g2 < L_IN) ? xb[g2] : 0.0f;
            __half h  = __float2half_rn(v);
            __half l  = __float2half_rn(v - __half2float(h));
            __half h2 = __float2half_rn(v2);
            __half l2 = __float2half_rn(v2 - __half2float(h2));
            xch[i] = h;  xcl[i] = l;
            xoh[i] = h2; xol[i] = l2;
        }
    }
    __syncthreads();

    // ---- per-lane address bases ----
    // A (ldmatrix): lane l -> row (l&7) + ((l>>3)&1)*8, k-byte ((l>>3)>>1)*16
    const int sub = lid >> 3;
    const uint32_t a_base = sbase + WS_OFF
        + (uint32_t)(((lid & 7) + (sub & 1) * 8) * A_STRIDE_B + (sub >> 1) * 16);
    // B: half index o = k0 + 2*tg + nw + 8*j + gid ; sel = parity (const per lane)
    const int sel = gid & 1;
    const uint32_t b_base = sbase + (sel ? XO_H_OFF : XC_H_OFF)
        + (uint32_t)(2 * (2 * tg + nw + gid - sel));

    float acc[5][4][4];
    #pragma unroll
    for (int i = 0; i < 5; i++)
        #pragma unroll
        for (int j = 0; j < 4; j++)
            #pragma unroll
            for (int c = 0; c < 4; c++) acc[i][j][c] = 0.0f;

    #pragma unroll 2
    for (int s = 0; s < NSTEPS; s++) {
        const uint32_t kb = (uint32_t)s * 32;   // k0 * 2 bytes

        // B fragments: b1[j] == b0[j+1], so only 5 hi + 5 lo distinct words
        uint32_t bh[5], bl[5];
        #pragma unroll
        for (int j = 0; j < 5; j++) {
            uint32_t a = b_base + kb + (uint32_t)(j * 16);
            bh[j] = lds32(a);
            bl[j] = lds32(a + 2176);
        }

        #pragma unroll
        for (int i = 0; i < 5; i++) {
            uint32_t ah[4];
            uint32_t aa = a_base + (uint32_t)(i * 16 * A_STRIDE_B) + kb;
            ldsm4(ah, aa);
            #pragma unroll
            for (int j = 0; j < 4; j++) {
                mma16816(acc[i][j], ah, bh[j], bh[j + 1]);
                mma16816(acc[i][j], ah, bl[j], bl[j + 1]);
            }
        }
    }

    // ---- epilogue: direct stores from fragments ----
    #pragma unroll
    for (int i = 0; i < 5; i++) {
        const int f0 = 16 * i + gid;
        float* o0 = out + ((size_t)b * N_FILT + f0) * P_OUT;
        float* o1 = out + ((size_t)b * N_FILT + f0 + 8) * P_OUT;
        #pragma unroll
        for (int j = 0; j < 4; j++) {
            int p = n0 + nw + 8 * j + 2 * tg;
            if (p < P_OUT) {
                *reinterpret_cast<float2*>(o0 + p) =
                    make_float2(acc[i][j][0], acc[i][j][1]);
                *reinterpret_cast<float2*>(o1 + p) =
                    make_float2(acc[i][j][2], acc[i][j][3]);
            }
        }
    }
}

// ================================ launch ================================
extern "C" void kernel_launch(void* const* d_in, const int* in_sizes, int n_in,
                              void* d_out, int out_size) {
    const float* x    = (const float*)d_in[0];
    const float* nf1  = (const float*)d_in[1];
    const float* nf2  = (const float*)d_in[2];
    const float* nf3  = (const float*)d_in[3];
    const float* nf4  = (const float*)d_in[4];
    const float* amp1 = (const float*)d_in[5];
    const float* amp2 = (const float*)d_in[6];
    float* out = (float*)d_out;

    static bool attr_set = false;
    if (!attr_set) {
        cudaFuncSetAttribute(conv_mma_kernel,
                             cudaFuncAttributeMaxDynamicSharedMemorySize, SMEM_TOTAL);
        attr_set = true;
    }

    build_filters_kernel<<<N_FILT, THREADS>>>(nf1, nf2, nf3, nf4, amp1, amp2);
    prep_w_kernel<<<MPAD, KPAD>>>();

    dim3 grid((P_OUT + NT - 1) / NT, N_BATCH);   // 250 x 8
    conv_mma_kernel<<<grid, THREADS, SMEM_TOTAL>>>(x, out);
}

// round 7
// speedup vs baseline: 6.1140x; 1.9387x over previous
#include <cuda_runtime.h>
#include <cuda_fp16.h>
#include <math_constants.h>
#include <cstdint>

#define N_FILT 80
#define FDIM   251
#define L_IN   64000
#define P_OUT  63750
#define N_BATCH 8

#define MPAD   128
#define KPAD   256
#define NT     256          // positions per CTA
#define THREADS 256
#define NSTEPS  16          // KPAD / 16

// A row stride padded to 528B (264 halves): 132 words = 4 banks shift/row
#define A_STRIDE_B 528
// dynamic smem layout (bytes)
#define WS_OFF   0
#define XC_OFF   42240      // 80 * 528
#define XO_OFF   43328      // +1088
#define SMEM_TOTAL 44416
#define XBUF 528

__device__ float  g_filters[N_FILT][FDIM];
__device__ __half g_wh[MPAD][KPAD];   // zero-initialized; rows >=80 stay zero

// ============================ PTX helpers ============================
__device__ __forceinline__ uint32_t smem_u32(const void* p) {
    uint32_t a;
    asm("{ .reg .u64 t; cvta.to.shared.u64 t, %1; cvt.u32.u64 %0, t; }"
        : "=r"(a) : "l"(p));
    return a;
}
__device__ __forceinline__ uint32_t lds32(uint32_t a) {
    uint32_t v;
    asm volatile("ld.shared.b32 %0, [%1];" : "=r"(v) : "r"(a));
    return v;
}
__device__ __forceinline__ void ldsm4(uint32_t* r, uint32_t a) {
    asm volatile("ldmatrix.sync.aligned.m8n8.x4.shared.b16 {%0,%1,%2,%3}, [%4];"
                 : "=r"(r[0]), "=r"(r[1]), "=r"(r[2]), "=r"(r[3]) : "r"(a));
}
__device__ __forceinline__ void mma16816(float* d, const uint32_t* a,
                                         uint32_t b0, uint32_t b1) {
    asm volatile(
        "mma.sync.aligned.m16n8k16.row.col.f32.f16.f16.f32 "
        "{%0,%1,%2,%3}, {%4,%5,%6,%7}, {%8,%9}, {%0,%1,%2,%3};"
        : "+f"(d[0]), "+f"(d[1]), "+f"(d[2]), "+f"(d[3])
        : "r"(a[0]), "r"(a[1]), "r"(a[2]), "r"(a[3]), "r"(b0), "r"(b1));
}

// ========================= filter construction =========================
__device__ __forceinline__ float blk_reduce(float v, int mode) {
    __shared__ float red[THREADS];
    int t = threadIdx.x;
    __syncthreads();
    red[t] = v;
    __syncthreads();
    #pragma unroll
    for (int s = THREADS / 2; s > 0; s >>= 1) {
        if (t < s) {
            float a = red[t], b = red[t + s];
            red[t] = (mode == 0) ? fmaxf(a, b) : (mode == 1) ? fminf(a, b) : (a + b);
        }
        __syncthreads();
    }
    float r = red[0];
    __syncthreads();
    return r;
}
__device__ __forceinline__ float norm_pm1(float v, bool act) {
    float mx = blk_reduce(act ? v : -CUDART_INF_F, 0);
    float mn = blk_reduce(act ? v :  CUDART_INF_F, 1);
    float y  = 2.0f * (v - mn) / (mx - mn + 1e-6f) - 1.0f;
    float s  = blk_reduce(act ? y : 0.0f, 2);
    return y - s * (1.0f / (float)FDIM);
}

__global__ void build_filters_kernel(const float* __restrict__ nf1,
                                     const float* __restrict__ nf2,
                                     const float* __restrict__ nf3,
                                     const float* __restrict__ nf4,
                                     const float* __restrict__ amp1,
                                     const float* __restrict__ amp2) {
    __shared__ float ir1[FDIM];
    __shared__ float ir2[FDIM];
    const int f = blockIdx.x;
    const int i = threadIdx.x;
    const bool act = (i < FDIM);
    const float FS = 16000.0f, MF = 50.0f / 16000.0f;
    const float PIF = 3.14159265358979323846f, TWO_PI = 6.28318530717958647692f;

    float f1 = fminf(fmaxf(fabsf(nf1[f]) + MF, 0.0f), 0.5f);
    float f2 = fminf(fmaxf(f1 + fabsf(nf2[f] - f1) + MF, 0.0f), 0.5f);
    float f3 = fminf(fmaxf(fabsf(nf3[f]) + MF, 0.0f), 0.5f);
    float f4 = fminf(fmaxf(f3 + fabsf(nf4[f] - f3) + MF, 0.0f), 0.5f);
    float a1 = fabsf(amp1[f]), a2 = fabsf(amp2[f]);
    float ti = act ? (float)(i + 1) * (1.0f / FS) : 0.0f;
    float t2 = ti * ti;
    {
        float F1 = f1 * FS, F2 = f2 * FS, fc = 0.5f * (F1 + F2), bw = F2 - F1;
        float pb = PIF * bw, ce = -2.0f * pb * pb;
        float v = a1 * expf(ce * t2) * cosf((TWO_PI * fc) * ti);
        v = norm_pm1(v, act);
        if (act) ir1[i] = v;
    }
    {
        float F1 = f3 * FS, F2 = f4 * FS, fc = 0.5f * (F1 + F2), bw = F2 - F1;
        float pb = PIF * bw, ce = -2.0f * pb * pb;
        float v = a2 * expf(ce * t2) * cosf((TWO_PI * fc) * ti);
        v = norm_pm1(v, act);
        if (act) ir2[i] = v;
    }
    __syncthreads();
    float c = 0.0f;
    if (act) {
        #pragma unroll 4
        for (int j = 0; j < FDIM; j++) {
            int idx = i + j - (FDIM / 2);
            if (idx >= 0 && idx < FDIM) c += ir1[idx] * ir2[j];
        }
    }
    c = norm_pm1(c, act);
    // write fp16 weights directly (rows >= 80 stay zero via static init)
    if (act) {
        float nv  = (float)i * ((float)FDIM / (float)(FDIM - 1));
        float win = 0.54f - 0.46f * cosf(TWO_PI * nv * (1.0f / (float)FDIM));
        float w = c * win;
        g_filters[f][i] = w;
        g_wh[f][i] = __float2half_rn(w);
    } else if (i < KPAD) {
        g_wh[f][i] = __ushort_as_half(0);   // zero K tail 251..255
    }
}

// ========================= main HMMA conv =========================
extern __shared__ __align__(16) char smraw[];

__global__ __launch_bounds__(THREADS) void conv_mma_kernel(const float* __restrict__ x,
                                                           float* __restrict__ out) {
    const int t   = threadIdx.x;
    const int wid = t >> 5;
    const int lid = t & 31;
    const int gid = lid >> 2;      // 0..7
    const int tg  = lid & 3;       // 0..3
    const int n0  = blockIdx.x * NT;
    const int b   = blockIdx.y;
    const int nw  = wid * 32;      // warp's position offset within tile

    const uint32_t sbase = smem_u32(smraw);

    // ---- load fp16 weights into smem, 528B padded row stride ----
    {
        const uint2* gh = reinterpret_cast<const uint2*>(&g_wh[0][0]);
        #pragma unroll
        for (int i = 0; i < 20; i++) {
            int idx = t + i * THREADS;          // 0..5119
            int m = idx >> 6, c = idx & 63;
            uint2 vh = gh[m * 64 + c];
            *reinterpret_cast<uint2*>(smraw + WS_OFF + m * A_STRIDE_B + c * 8) = vh;
        }
    }
    // ---- load x window (fp16), plus 1-half-shifted copy ----
    {
        const float* xb = x + (size_t)b * L_IN;
        __half* xc = reinterpret_cast<__half*>(smraw + XC_OFF);
        __half* xo = reinterpret_cast<__half*>(smraw + XO_OFF);
        #pragma unroll
        for (int i = t; i < XBUF; i += THREADS) {
            int g  = n0 + i;
            float v  = (g < L_IN) ? xb[g] : 0.0f;
            int g2 = g + 1;
            float v2 = (g2 < L_IN) ? xb[g2] : 0.0f;
            xc[i] = __float2half_rn(v);
            xo[i] = __float2half_rn(v2);
        }
    }
    __syncthreads();

    // ---- per-lane address bases ----
    // A (ldmatrix): lane l -> row (l&7) + ((l>>3)&1)*8, k-byte ((l>>3)>>1)*16
    const int sub = lid >> 3;
    const uint32_t a_base = sbase + WS_OFF
        + (uint32_t)(((lid & 7) + (sub & 1) * 8) * A_STRIDE_B + (sub >> 1) * 16);
    // B: half index o = k0 + 2*tg + nw + 8*j + gid ; sel = parity (const per lane)
    const int sel = gid & 1;
    const uint32_t b_base = sbase + (sel ? XO_OFF : XC_OFF)
        + (uint32_t)(2 * (2 * tg + nw + gid - sel));

    float acc[5][4][4];
    #pragma unroll
    for (int i = 0; i < 5; i++)
        #pragma unroll
        for (int j = 0; j < 4; j++)
            #pragma unroll
            for (int c = 0; c < 4; c++) acc[i][j][c] = 0.0f;

    #pragma unroll 2
    for (int s = 0; s < NSTEPS; s++) {
        const uint32_t kb = (uint32_t)s * 32;   // k0 * 2 bytes

        // B fragments: b1[j] == b0[j+1], so only 5 distinct words
        uint32_t bh[5];
        #pragma unroll
        for (int j = 0; j < 5; j++) {
            bh[j] = lds32(b_base + kb + (uint32_t)(j * 16));
        }

        #pragma unroll
        for (int i = 0; i < 5; i++) {
            uint32_t ah[4];
            ldsm4(ah, a_base + (uint32_t)(i * 16 * A_STRIDE_B) + kb);
            #pragma unroll
            for (int j = 0; j < 4; j++) {
                mma16816(acc[i][j], ah, bh[j], bh[j + 1]);
            }
        }
    }

    // ---- epilogue: direct stores from fragments ----
    #pragma unroll
    for (int i = 0; i < 5; i++) {
        const int f0 = 16 * i + gid;
        float* o0 = out + ((size_t)b * N_FILT + f0) * P_OUT;
        float* o1 = out + ((size_t)b * N_FILT + f0 + 8) * P_OUT;
        #pragma unroll
        for (int j = 0; j < 4; j++) {
            int p = n0 + nw + 8 * j + 2 * tg;
            if (p < P_OUT) {
                *reinterpret_cast<float2*>(o0 + p) =
                    make_float2(acc[i][j][0], acc[i][j][1]);
                *reinterpret_cast<float2*>(o1 + p) =
                    make_float2(acc[i][j][2], acc[i][j][3]);
            }
        }
    }
}

// ================================ launch ================================
extern "C" void kernel_launch(void* const* d_in, const int* in_sizes, int n_in,
                              void* d_out, int out_size) {
    const float* x    = (const float*)d_in[0];
    const float* nf1  = (const float*)d_in[1];
    const float* nf2  = (const float*)d_in[2];
    const float* nf3  = (const float*)d_in[3];
    const float* nf4  = (const float*)d_in[4];
    const float* amp1 = (const float*)d_in[5];
    const float* amp2 = (const float*)d_in[6];
    float* out = (float*)d_out;

    static bool attr_set = false;
    if (!attr_set) {
        cudaFuncSetAttribute(conv_mma_kernel,
                             cudaFuncAttributeMaxDynamicSharedMemorySize, SMEM_TOTAL);
        attr_set = true;
    }

    build_filters_kernel<<<N_FILT, THREADS>>>(nf1, nf2, nf3, nf4, amp1, amp2);

    dim3 grid((P_OUT + NT - 1) / NT, N_BATCH);   // 250 x 8
    conv_mma_kernel<<<grid, THREADS, SMEM_TOTAL>>>(x, out);
}